// round 4
// baseline (speedup 1.0000x reference)
#include <cuda_runtime.h>
#include <cuda_fp16.h>
#include <cstdint>

#define N_USERS 100000
#define N_ITEMS 200000
#define N_NODES 300000
#define EMB     64
#define NNZ     9600000
#define SCAN_B  1024
#define NB      ((N_NODES + SCAN_B - 1) / SCAN_B)   // 293
#define SPMM_BLOCKS (148 * 8)

// -------- static device scratch (allocation-free) --------
__device__ __half g_ego[2][(size_t)N_NODES * EMB];   // ping-pong fp16 layer embeddings
__device__ int2   g_edge[NNZ];                       // packed (col, val-bits)
__device__ int    g_rowptr[N_NODES + 1];
__device__ int    g_cursor[N_NODES];
__device__ int    g_counts[N_NODES];
__device__ int    g_bsums[NB];

// -------- 1) zero counts --------
__global__ void k_zero_counts() {
    int i = blockIdx.x * blockDim.x + threadIdx.x;
    if (i < N_NODES) g_counts[i] = 0;
}

// -------- 2) init: acc(=d_out) = ego0 (fp32), g_ego[0] = fp16(ego0) --------
__global__ void k_init(const float4* __restrict__ user4,
                       const float4* __restrict__ item4,
                       float4* __restrict__ out4) {
    const int n4  = N_NODES * EMB / 4;         // 4.8M float4
    const int nu4 = N_USERS * EMB / 4;         // 1.6M
    int i = blockIdx.x * blockDim.x + threadIdx.x;
    if (i >= n4) return;
    float4 v = (i < nu4) ? __ldcs(&user4[i]) : __ldcs(&item4[i - nu4]);
    __stcs(&out4[i], v);                       // acc starts at layer-0 embedding (exact)
    half2* h = reinterpret_cast<half2*>(g_ego[0]);
    h[2 * i]     = __floats2half2_rn(v.x, v.y);
    h[2 * i + 1] = __floats2half2_rn(v.z, v.w);
}

// -------- 3) histogram of rows --------
__global__ void k_hist(const int* __restrict__ rows) {
    int e = blockIdx.x * blockDim.x + threadIdx.x;
    if (e < NNZ) atomicAdd(&g_counts[__ldcs(&rows[e])], 1);
}

// -------- 4) exclusive scan (3 kernels) --------
__global__ void k_scan1() {
    __shared__ int sh[SCAN_B];
    int tid = threadIdx.x;
    int gid = blockIdx.x * SCAN_B + tid;
    int v = (gid < N_NODES) ? g_counts[gid] : 0;
    sh[tid] = v;
    __syncthreads();
    for (int off = 1; off < SCAN_B; off <<= 1) {
        int t = (tid >= off) ? sh[tid - off] : 0;
        __syncthreads();
        sh[tid] += t;
        __syncthreads();
    }
    int incl = sh[tid];
    if (gid < N_NODES) g_rowptr[gid] = incl - v;     // block-local exclusive
    if (tid == SCAN_B - 1) g_bsums[blockIdx.x] = incl;
}

__global__ void k_scan2() {
    __shared__ int sh[512];
    int tid = threadIdx.x;   // blockDim = 512, NB = 293 <= 512
    int v = (tid < NB) ? g_bsums[tid] : 0;
    sh[tid] = v;
    __syncthreads();
    for (int off = 1; off < 512; off <<= 1) {
        int t = (tid >= off) ? sh[tid - off] : 0;
        __syncthreads();
        sh[tid] += t;
        __syncthreads();
    }
    if (tid < NB) g_bsums[tid] = sh[tid] - v;        // exclusive
}

__global__ void k_scan3() {
    int gid = blockIdx.x * SCAN_B + threadIdx.x;
    if (gid < N_NODES) {
        int p = g_rowptr[gid] + g_bsums[blockIdx.x];
        g_rowptr[gid] = p;
        g_cursor[gid] = p;                            // scatter cursors start at row base
    }
    if (gid == 0) g_rowptr[N_NODES] = NNZ;
}

// -------- 5) scatter COO -> CSR (packed meta) --------
__global__ void k_scatter(const int* __restrict__ rows,
                          const int* __restrict__ cols,
                          const float* __restrict__ vals) {
    int e = blockIdx.x * blockDim.x + threadIdx.x;
    if (e >= NNZ) return;
    int r = __ldcs(&rows[e]);
    int idx = atomicAdd(&g_cursor[r], 1);
    __stcs(&g_edge[idx], make_int2(__ldcs(&cols[e]), __float_as_int(__ldcs(&vals[e]))));
}

// -------- 6) persistent SpMM: 8 lanes/edge, 4 edges per LDG.128 --------
// lane = group*8 + sub; group g handles edge (jj*4+g); lane loads uint4 = 16B
// slice [sub*16, sub*16+16) of the 128B fp16 row. Butterfly-reduce across groups.
// last==0: eout = fp16(a); acc += a
// last==1: acc = (acc + a) * 0.25   (fused final mean; no eout write)
__global__ __launch_bounds__(256) void k_spmm(int pin, int last, float4* __restrict__ acc4) {
    const uint4* __restrict__ ein = reinterpret_cast<const uint4*>(g_ego[pin]);   // 8 uint4 per row
    uint4* __restrict__ eout      = reinterpret_cast<uint4*>(g_ego[1 - pin]);

    const int lane  = threadIdx.x & 31;
    const int group = lane >> 3;          // 0..3 : which of 4 concurrent edges
    const int sub   = lane & 7;           // 0..7 : 16B slice within the row
    const int warp0  = (blockIdx.x * blockDim.x + threadIdx.x) >> 5;
    const int nwarps = (gridDim.x * blockDim.x) >> 5;

    for (int row = warp0; row < N_NODES; row += nwarps) {
        int start = g_rowptr[row];
        int end   = g_rowptr[row + 1];

        float2 a0 = make_float2(0.f, 0.f), a1 = a0, a2 = a0, a3 = a0;

        for (int base = start; base < end; base += 32) {
            int rem = end - base;
            int c = 0; float v = 0.f;
            if (lane < rem) {                         // coalesced 256B meta load (32 edges)
                int2 ev = __ldcs(&g_edge[base + lane]);
                c = ev.x;
                v = __int_as_float(ev.y);
            }
            int niter = (min(rem, 32) + 3) >> 2;      // 4 edges per iteration
            for (int jj = 0; jj < niter; jj++) {
                int src = (jj << 2) + group;          // edge slot for this lane's group
                int   cj = __shfl_sync(0xffffffffu, c, src);
                float vj = __shfl_sync(0xffffffffu, v, src);   // 0 beyond rem -> contributes 0
                uint4 x = __ldg(ein + (size_t)cj * 8 + sub);   // LDG.128: 4 rows per warp-instr
                float2 f;
                f = __half22float2(*reinterpret_cast<half2*>(&x.x));
                a0.x = fmaf(vj, f.x, a0.x); a0.y = fmaf(vj, f.y, a0.y);
                f = __half22float2(*reinterpret_cast<half2*>(&x.y));
                a1.x = fmaf(vj, f.x, a1.x); a1.y = fmaf(vj, f.y, a1.y);
                f = __half22float2(*reinterpret_cast<half2*>(&x.z));
                a2.x = fmaf(vj, f.x, a2.x); a2.y = fmaf(vj, f.y, a2.y);
                f = __half22float2(*reinterpret_cast<half2*>(&x.w));
                a3.x = fmaf(vj, f.x, a3.x); a3.y = fmaf(vj, f.y, a3.y);
            }
        }

        // butterfly reduce across the 4 edge-groups (lanes differing in bits 3,4)
        #pragma unroll
        for (int off = 8; off <= 16; off <<= 1) {
            a0.x += __shfl_xor_sync(0xffffffffu, a0.x, off);
            a0.y += __shfl_xor_sync(0xffffffffu, a0.y, off);
            a1.x += __shfl_xor_sync(0xffffffffu, a1.x, off);
            a1.y += __shfl_xor_sync(0xffffffffu, a1.y, off);
            a2.x += __shfl_xor_sync(0xffffffffu, a2.x, off);
            a2.y += __shfl_xor_sync(0xffffffffu, a2.y, off);
            a3.x += __shfl_xor_sync(0xffffffffu, a3.x, off);
            a3.y += __shfl_xor_sync(0xffffffffu, a3.y, off);
        }

        if (group == 0) {                 // lanes 0..7 hold the full row sum per slice
            // acc row: 64 floats = 16 float4; this lane owns float4 slots [sub*2, sub*2+2)
            size_t ob = (size_t)row * 16 + sub * 2;
            float4 t0 = __ldcs(&acc4[ob]);
            float4 t1 = __ldcs(&acc4[ob + 1]);
            t0.x += a0.x; t0.y += a0.y; t0.z += a1.x; t0.w += a1.y;
            t1.x += a2.x; t1.y += a2.y; t1.z += a3.x; t1.w += a3.y;
            if (last) {
                t0.x *= 0.25f; t0.y *= 0.25f; t0.z *= 0.25f; t0.w *= 0.25f;
                t1.x *= 0.25f; t1.y *= 0.25f; t1.z *= 0.25f; t1.w *= 0.25f;
            } else {
                uint4 h;
                *reinterpret_cast<half2*>(&h.x) = __floats2half2_rn(a0.x, a0.y);
                *reinterpret_cast<half2*>(&h.y) = __floats2half2_rn(a1.x, a1.y);
                *reinterpret_cast<half2*>(&h.z) = __floats2half2_rn(a2.x, a2.y);
                *reinterpret_cast<half2*>(&h.w) = __floats2half2_rn(a3.x, a3.y);
                eout[(size_t)row * 8 + sub] = h;     // next layer's gather operand
            }
            __stcs(&acc4[ob], t0);
            __stcs(&acc4[ob + 1], t1);
        }
    }
}

extern "C" void kernel_launch(void* const* d_in, const int* in_sizes, int n_in,
                              void* d_out, int out_size) {
    const float* user = (const float*)d_in[0];
    const float* item = (const float*)d_in[1];
    const int*   rows = (const int*)d_in[2];
    const int*   cols = (const int*)d_in[3];
    const float* vals = (const float*)d_in[4];
    float* out = (float*)d_out;

    const int T = 256;
    const int n4      = N_NODES * EMB / 4;
    const int gInit   = (n4 + T - 1) / T;
    const int gNodes  = (N_NODES + T - 1) / T;
    const int gEdges  = (NNZ + T - 1) / T;

    k_zero_counts<<<gNodes, T>>>();
    k_init<<<gInit, T>>>((const float4*)user, (const float4*)item, (float4*)out);
    k_hist<<<gEdges, T>>>(rows);
    k_scan1<<<NB, SCAN_B>>>();
    k_scan2<<<1, 512>>>();
    k_scan3<<<NB, SCAN_B>>>();
    k_scatter<<<gEdges, T>>>(rows, cols, vals);

    k_spmm<<<SPMM_BLOCKS, T>>>(0, 0, (float4*)out);   // layer 1
    k_spmm<<<SPMM_BLOCKS, T>>>(1, 0, (float4*)out);   // layer 2
    k_spmm<<<SPMM_BLOCKS, T>>>(0, 1, (float4*)out);   // layer 3 + fused mean
}

// round 5
// speedup vs baseline: 1.1007x; 1.1007x over previous
#include <cuda_runtime.h>
#include <cuda_fp16.h>
#include <cstdint>

#define N_USERS 100000
#define N_ITEMS 200000
#define N_NODES 300000
#define EMB     64
#define NNZ     9600000
#define SCAN_B  1024
#define NB      ((N_NODES + SCAN_B - 1) / SCAN_B)   // 293
#define SPMM_BLOCKS (148 * 8)

// -------- static device scratch (allocation-free) --------
__device__ __half g_ego[3][(size_t)N_NODES * EMB];   // ego0 / e1 / e2 (fp16)
__device__ int2   g_edge[NNZ];                       // packed (col, val-bits)
__device__ int    g_rowptr[N_NODES + 1];
__device__ int    g_cursor[N_NODES];
__device__ int    g_counts[N_NODES];
__device__ int    g_bsums[NB];

// -------- 1) zero counts --------
__global__ void k_zero_counts() {
    int i = blockIdx.x * blockDim.x + threadIdx.x;
    if (i < N_NODES) g_counts[i] = 0;
}

// -------- 2) init: g_ego[0] = fp16(cat(user,item));  (no d_out write) --------
__global__ void k_init(const float4* __restrict__ user4,
                       const float4* __restrict__ item4) {
    const int n4  = N_NODES * EMB / 4;         // 4.8M float4
    const int nu4 = N_USERS * EMB / 4;         // 1.6M
    int i = blockIdx.x * blockDim.x + threadIdx.x;
    if (i >= n4) return;
    float4 v = (i < nu4) ? __ldcs(&user4[i]) : __ldcs(&item4[i - nu4]);
    half2* h = reinterpret_cast<half2*>(g_ego[0]);
    h[2 * i]     = __floats2half2_rn(v.x, v.y);
    h[2 * i + 1] = __floats2half2_rn(v.z, v.w);
}

// -------- 3) histogram of rows --------
__global__ void k_hist(const int* __restrict__ rows) {
    int e = blockIdx.x * blockDim.x + threadIdx.x;
    if (e < NNZ) atomicAdd(&g_counts[__ldcs(&rows[e])], 1);
}

// -------- 4) exclusive scan (3 kernels) --------
__global__ void k_scan1() {
    __shared__ int sh[SCAN_B];
    int tid = threadIdx.x;
    int gid = blockIdx.x * SCAN_B + tid;
    int v = (gid < N_NODES) ? g_counts[gid] : 0;
    sh[tid] = v;
    __syncthreads();
    for (int off = 1; off < SCAN_B; off <<= 1) {
        int t = (tid >= off) ? sh[tid - off] : 0;
        __syncthreads();
        sh[tid] += t;
        __syncthreads();
    }
    int incl = sh[tid];
    if (gid < N_NODES) g_rowptr[gid] = incl - v;     // block-local exclusive
    if (tid == SCAN_B - 1) g_bsums[blockIdx.x] = incl;
}

__global__ void k_scan2() {
    __shared__ int sh[512];
    int tid = threadIdx.x;   // blockDim = 512, NB = 293 <= 512
    int v = (tid < NB) ? g_bsums[tid] : 0;
    sh[tid] = v;
    __syncthreads();
    for (int off = 1; off < 512; off <<= 1) {
        int t = (tid >= off) ? sh[tid - off] : 0;
        __syncthreads();
        sh[tid] += t;
        __syncthreads();
    }
    if (tid < NB) g_bsums[tid] = sh[tid] - v;        // exclusive
}

__global__ void k_scan3() {
    int gid = blockIdx.x * SCAN_B + threadIdx.x;
    if (gid < N_NODES) {
        int p = g_rowptr[gid] + g_bsums[blockIdx.x];
        g_rowptr[gid] = p;
        g_cursor[gid] = p;                            // scatter cursors start at row base
    }
    if (gid == 0) g_rowptr[N_NODES] = NNZ;
}

// -------- 5) scatter COO -> CSR (packed meta) --------
__global__ void k_scatter(const int* __restrict__ rows,
                          const int* __restrict__ cols,
                          const float* __restrict__ vals) {
    int e = blockIdx.x * blockDim.x + threadIdx.x;
    if (e >= NNZ) return;
    int r = __ldcs(&rows[e]);
    int idx = atomicAdd(&g_cursor[r], 1);
    __stcs(&g_edge[idx], make_int2(__ldcs(&cols[e]), __float_as_int(__ldcs(&vals[e]))));
}

// -------- shared SpMM row-accumulate body (R3-proven gather shape) --------
__device__ __forceinline__ float2 spmm_row(const half2* __restrict__ ein,
                                           int start, int end, int lane) {
    float2 a = make_float2(0.f, 0.f);
    for (int base = start; base < end; base += 32) {
        int rem = end - base;
        int c = 0; float v = 0.f;
        if (lane < rem) {                    // coalesced 8B meta load for up to 32 edges
            int2 ev = __ldcs(&g_edge[base + lane]);
            c = ev.x;
            v = __int_as_float(ev.y);
        }
        if (rem >= 32) {
            #pragma unroll
            for (int j = 0; j < 32; j++) {
                int   cj = __shfl_sync(0xffffffffu, c, j);
                float vj = __shfl_sync(0xffffffffu, v, j);
                float2 x = __half22float2(__ldg(ein + (size_t)cj * 32 + lane)); // 128B/warp gather
                a.x = fmaf(vj, x.x, a.x);
                a.y = fmaf(vj, x.y, a.y);
            }
        } else {
            for (int j = 0; j < rem; j++) {
                int   cj = __shfl_sync(0xffffffffu, c, j);
                float vj = __shfl_sync(0xffffffffu, v, j);
                float2 x = __half22float2(__ldg(ein + (size_t)cj * 32 + lane));
                a.x = fmaf(vj, x.x, a.x);
                a.y = fmaf(vj, x.y, a.y);
            }
        }
    }
    return a;
}

// -------- 6a) mid layer: eout = fp16(A @ ein); no acc traffic --------
__global__ __launch_bounds__(256) void k_spmm_mid(int pin, int pout) {
    const half2* __restrict__ ein = reinterpret_cast<const half2*>(g_ego[pin]);
    half2* __restrict__ eout      = reinterpret_cast<half2*>(g_ego[pout]);

    const int lane   = threadIdx.x & 31;
    const int warp0  = (blockIdx.x * blockDim.x + threadIdx.x) >> 5;
    const int nwarps = (gridDim.x * blockDim.x) >> 5;

    for (int row = warp0; row < N_NODES; row += nwarps) {
        float2 a = spmm_row(ein, g_rowptr[row], g_rowptr[row + 1], lane);
        eout[(size_t)row * 32 + lane] = __floats2half2_rn(a.x, a.y);
    }
}

// -------- 6b) last layer, fully fused:
// out[row] = 0.25 * ( emb[row] + e1[row] + e2[row] + (A @ e2)[row] ) --------
__global__ __launch_bounds__(256) void k_spmm_last(const float2* __restrict__ user2,
                                                   const float2* __restrict__ item2,
                                                   float2* __restrict__ out2) {
    const half2* __restrict__ e1 = reinterpret_cast<const half2*>(g_ego[1]);
    const half2* __restrict__ e2 = reinterpret_cast<const half2*>(g_ego[2]);

    const int lane   = threadIdx.x & 31;
    const int warp0  = (blockIdx.x * blockDim.x + threadIdx.x) >> 5;
    const int nwarps = (gridDim.x * blockDim.x) >> 5;

    for (int row = warp0; row < N_NODES; row += nwarps) {
        float2 a = spmm_row(e2, g_rowptr[row], g_rowptr[row + 1], lane);

        size_t o = (size_t)row * 32 + lane;
        float2 base = (row < N_USERS)
                    ? __ldcs(user2 + (size_t)row * 32 + lane)
                    : __ldcs(item2 + (size_t)(row - N_USERS) * 32 + lane);
        float2 f1 = __half22float2(e1[o]);
        float2 f2 = __half22float2(e2[o]);
        float2 r;
        r.x = (base.x + f1.x + f2.x + a.x) * 0.25f;
        r.y = (base.y + f1.y + f2.y + a.y) * 0.25f;
        __stcs(&out2[o], r);
    }
}

extern "C" void kernel_launch(void* const* d_in, const int* in_sizes, int n_in,
                              void* d_out, int out_size) {
    const float* user = (const float*)d_in[0];
    const float* item = (const float*)d_in[1];
    const int*   rows = (const int*)d_in[2];
    const int*   cols = (const int*)d_in[3];
    const float* vals = (const float*)d_in[4];
    float* out = (float*)d_out;

    const int T = 256;
    const int n4      = N_NODES * EMB / 4;
    const int gInit   = (n4 + T - 1) / T;
    const int gNodes  = (N_NODES + T - 1) / T;
    const int gEdges  = (NNZ + T - 1) / T;

    k_zero_counts<<<gNodes, T>>>();
    k_init<<<gInit, T>>>((const float4*)user, (const float4*)item);
    k_hist<<<gEdges, T>>>(rows);
    k_scan1<<<NB, SCAN_B>>>();
    k_scan2<<<1, 512>>>();
    k_scan3<<<NB, SCAN_B>>>();
    k_scatter<<<gEdges, T>>>(rows, cols, vals);

    k_spmm_mid<<<SPMM_BLOCKS, T>>>(0, 1);             // layer 1: ego0 -> e1
    k_spmm_mid<<<SPMM_BLOCKS, T>>>(1, 2);             // layer 2: e1   -> e2
    k_spmm_last<<<SPMM_BLOCKS, T>>>((const float2*)user, (const float2*)item,
                                    (float2*)out);    // layer 3 + full fused mean
}

// round 6
// speedup vs baseline: 1.1710x; 1.0638x over previous
#include <cuda_runtime.h>
#include <cuda_fp16.h>
#include <cstdint>

#define N_USERS 100000
#define N_ITEMS 200000
#define N_NODES 300000
#define EMB     64
#define NNZ     9600000
#define SCAN_B  1024
#define NB      ((N_NODES + SCAN_B - 1) / SCAN_B)   // 293
#define SPMM_BLOCKS (148 * 8)
#define WARPS_PER_BLOCK 8

// -------- static device scratch (allocation-free) --------
__device__ __half g_ego[3][(size_t)N_NODES * EMB];   // ego0 / e1 / e2 (fp16)
__device__ int2   g_edge[NNZ];                       // packed (col, half2(val,val))
__device__ int    g_rowptr[N_NODES + 1];
__device__ int    g_cursor[N_NODES];
__device__ int    g_counts[N_NODES];
__device__ int    g_bsums[NB];

// -------- 1) zero counts --------
__global__ void k_zero_counts() {
    int i = blockIdx.x * blockDim.x + threadIdx.x;
    if (i < N_NODES) g_counts[i] = 0;
}

// -------- 2) init: g_ego[0] = fp16(cat(user,item)) --------
__global__ void k_init(const float4* __restrict__ user4,
                       const float4* __restrict__ item4) {
    const int n4  = N_NODES * EMB / 4;         // 4.8M float4
    const int nu4 = N_USERS * EMB / 4;         // 1.6M
    int i = blockIdx.x * blockDim.x + threadIdx.x;
    if (i >= n4) return;
    float4 v = (i < nu4) ? __ldcs(&user4[i]) : __ldcs(&item4[i - nu4]);
    half2* h = reinterpret_cast<half2*>(g_ego[0]);
    h[2 * i]     = __floats2half2_rn(v.x, v.y);
    h[2 * i + 1] = __floats2half2_rn(v.z, v.w);
}

// -------- 3) histogram of rows --------
__global__ void k_hist(const int* __restrict__ rows) {
    int e = blockIdx.x * blockDim.x + threadIdx.x;
    if (e < NNZ) atomicAdd(&g_counts[__ldcs(&rows[e])], 1);
}

// -------- 4) exclusive scan (3 kernels) --------
__global__ void k_scan1() {
    __shared__ int sh[SCAN_B];
    int tid = threadIdx.x;
    int gid = blockIdx.x * SCAN_B + tid;
    int v = (gid < N_NODES) ? g_counts[gid] : 0;
    sh[tid] = v;
    __syncthreads();
    for (int off = 1; off < SCAN_B; off <<= 1) {
        int t = (tid >= off) ? sh[tid - off] : 0;
        __syncthreads();
        sh[tid] += t;
        __syncthreads();
    }
    int incl = sh[tid];
    if (gid < N_NODES) g_rowptr[gid] = incl - v;     // block-local exclusive
    if (tid == SCAN_B - 1) g_bsums[blockIdx.x] = incl;
}

__global__ void k_scan2() {
    __shared__ int sh[512];
    int tid = threadIdx.x;   // blockDim = 512, NB = 293 <= 512
    int v = (tid < NB) ? g_bsums[tid] : 0;
    sh[tid] = v;
    __syncthreads();
    for (int off = 1; off < 512; off <<= 1) {
        int t = (tid >= off) ? sh[tid - off] : 0;
        __syncthreads();
        sh[tid] += t;
        __syncthreads();
    }
    if (tid < NB) g_bsums[tid] = sh[tid] - v;        // exclusive
}

__global__ void k_scan3() {
    int gid = blockIdx.x * SCAN_B + threadIdx.x;
    if (gid < N_NODES) {
        int p = g_rowptr[gid] + g_bsums[blockIdx.x];
        g_rowptr[gid] = p;
        g_cursor[gid] = p;                            // scatter cursors start at row base
    }
    if (gid == 0) g_rowptr[N_NODES] = NNZ;
}

// -------- 5) scatter COO -> CSR (col, duplicated-half2 val) --------
__global__ void k_scatter(const int* __restrict__ rows,
                          const int* __restrict__ cols,
                          const float* __restrict__ vals) {
    int e = blockIdx.x * blockDim.x + threadIdx.x;
    if (e >= NNZ) return;
    int r = __ldcs(&rows[e]);
    int idx = atomicAdd(&g_cursor[r], 1);
    half2 hv = __float2half2_rn(__ldcs(&vals[e]));    // (v, v) fp16
    __stcs(&g_edge[idx], make_int2(__ldcs(&cols[e]), *reinterpret_cast<int*>(&hv)));
}

// -------- SpMM row body: smem-broadcast meta + HFMA2 accumulate --------
// smeta: per-warp double-buffered staging [2][32] int2
__device__ __forceinline__ float2 spmm_row(const half2* __restrict__ ein,
                                           int2 (*smeta)[32],
                                           int start, int end, int lane) {
    float2 acc = make_float2(0.f, 0.f);
    int p = 0;
    for (int base = start; base < end; base += 32, p ^= 1) {
        int rem = end - base;
        int2 ev = make_int2(0, 0);
        if (lane < rem) ev = __ldcs(&g_edge[base + lane]);   // coalesced 256B meta load
        smeta[p][lane] = ev;
        __syncwarp();

        half2 a = __float2half2_rn(0.f);                      // fp16 chunk accumulator
        if (rem >= 32) {
            #pragma unroll
            for (int j = 0; j < 32; j++) {
                int2 e = smeta[p][j];                          // broadcast LDS (8B)
                half2 v2 = *reinterpret_cast<half2*>(&e.y);
                half2 x  = __ldg(ein + e.x * 32 + lane);       // 128B/warp, 1 line
                a = __hfma2(v2, x, a);
            }
        } else {
            for (int j = 0; j < rem; j++) {
                int2 e = smeta[p][j];
                half2 v2 = *reinterpret_cast<half2*>(&e.y);
                half2 x  = __ldg(ein + e.x * 32 + lane);
                a = __hfma2(v2, x, a);
            }
        }
        float2 af = __half22float2(a);                         // flush chunk to fp32
        acc.x += af.x;
        acc.y += af.y;
    }
    return acc;
}

// -------- 6a) mid layer: eout = fp16(A @ ein) --------
__global__ __launch_bounds__(256) void k_spmm_mid(int pin, int pout) {
    __shared__ int2 smeta[WARPS_PER_BLOCK][2][32];
    const half2* __restrict__ ein = reinterpret_cast<const half2*>(g_ego[pin]);
    half2* __restrict__ eout      = reinterpret_cast<half2*>(g_ego[pout]);

    const int lane   = threadIdx.x & 31;
    const int wid    = threadIdx.x >> 5;
    const int warp0  = (blockIdx.x * blockDim.x + threadIdx.x) >> 5;
    const int nwarps = (gridDim.x * blockDim.x) >> 5;

    for (int row = warp0; row < N_NODES; row += nwarps) {
        float2 a = spmm_row(ein, smeta[wid], g_rowptr[row], g_rowptr[row + 1], lane);
        eout[(size_t)row * 32 + lane] = __floats2half2_rn(a.x, a.y);
    }
}

// -------- 6b) last layer, fully fused:
// out[row] = 0.25 * ( emb[row] + e1[row] + e2[row] + (A @ e2)[row] ) --------
__global__ __launch_bounds__(256) void k_spmm_last(const float2* __restrict__ user2,
                                                   const float2* __restrict__ item2,
                                                   float2* __restrict__ out2) {
    __shared__ int2 smeta[WARPS_PER_BLOCK][2][32];
    const half2* __restrict__ e1 = reinterpret_cast<const half2*>(g_ego[1]);
    const half2* __restrict__ e2 = reinterpret_cast<const half2*>(g_ego[2]);

    const int lane   = threadIdx.x & 31;
    const int wid    = threadIdx.x >> 5;
    const int warp0  = (blockIdx.x * blockDim.x + threadIdx.x) >> 5;
    const int nwarps = (gridDim.x * blockDim.x) >> 5;

    for (int row = warp0; row < N_NODES; row += nwarps) {
        float2 a = spmm_row(e2, smeta[wid], g_rowptr[row], g_rowptr[row + 1], lane);

        size_t o = (size_t)row * 32 + lane;
        float2 base = (row < N_USERS)
                    ? __ldcs(user2 + (size_t)row * 32 + lane)
                    : __ldcs(item2 + (size_t)(row - N_USERS) * 32 + lane);
        float2 f1 = __half22float2(e1[o]);
        float2 f2 = __half22float2(e2[o]);
        float2 r;
        r.x = (base.x + f1.x + f2.x + a.x) * 0.25f;
        r.y = (base.y + f1.y + f2.y + a.y) * 0.25f;
        __stcs(&out2[o], r);
    }
}

extern "C" void kernel_launch(void* const* d_in, const int* in_sizes, int n_in,
                              void* d_out, int out_size) {
    const float* user = (const float*)d_in[0];
    const float* item = (const float*)d_in[1];
    const int*   rows = (const int*)d_in[2];
    const int*   cols = (const int*)d_in[3];
    const float* vals = (const float*)d_in[4];
    float* out = (float*)d_out;

    const int T = 256;
    const int n4      = N_NODES * EMB / 4;
    const int gInit   = (n4 + T - 1) / T;
    const int gNodes  = (N_NODES + T - 1) / T;
    const int gEdges  = (NNZ + T - 1) / T;

    k_zero_counts<<<gNodes, T>>>();
    k_init<<<gInit, T>>>((const float4*)user, (const float4*)item);
    k_hist<<<gEdges, T>>>(rows);
    k_scan1<<<NB, SCAN_B>>>();
    k_scan2<<<1, 512>>>();
    k_scan3<<<NB, SCAN_B>>>();
    k_scatter<<<gEdges, T>>>(rows, cols, vals);

    k_spmm_mid<<<SPMM_BLOCKS, T>>>(0, 1);             // layer 1: ego0 -> e1
    k_spmm_mid<<<SPMM_BLOCKS, T>>>(1, 2);             // layer 2: e1   -> e2
    k_spmm_last<<<SPMM_BLOCKS, T>>>((const float2*)user, (const float2*)item,
                                    (float2*)out);    // layer 3 + full fused mean
}